// round 15
// baseline (speedup 1.0000x reference)
#include <cuda_runtime.h>
#include <cuda_fp16.h>

#define NN 10000
#define EE 160000
#define BB 8
#define TT 12
#define HH 64
#define TS 3
#define T0 9
#define ROWS (TS*NN*BB)   /* 240000 rows of 64 features */
#define NB  (BB*NN)       /* 80000 (n,b) rows */
#define KD  192           /* stage1 K = 3t * 64ci */
#define P1  200           /* smem pitch (halves) for K=192 tiles */
#define P2  136           /* smem pitch for K=128 tiles */
#define DSTR 64           /* fixed edge-table stride per node */

typedef unsigned long long ull;
typedef unsigned int uint;

/* ---------------- device scratch (no allocs allowed) ---------------- */
__device__ float  g_deg[NN];
__device__ float  g_self[NN];
__device__ float  g_dinv[NN];
__device__ int    g_cnt[NN];
__device__ ull    g_edge[NN * DSTR];    /* packed (src low, w high), slot table */
__device__ uint4  g_h1h[TS * NN * 64];  /* fp16 h1: [t][n][b][64]  30.7MB */
__device__ __half g_h2h[(size_t)NB * KD];  /* fp16 h2: [nb][t*64+ci] 30.7MB */
__device__ __half g_B1h[128 * P1];      /* stage1 weights B^T padded */
__device__ __half g_B2h[64 * P2];       /* stage2 weights B^T padded */

/* ---------------- PDL ---------------- */
__device__ __forceinline__ void pdl_wait() {
    asm volatile("griddepcontrol.wait;" ::: "memory");
}

/* ---------------- packed f32x2 helpers ---------------- */
__device__ __forceinline__ ull fma2(ull a, ull b, ull c) {
    ull d;
    asm("fma.rn.f32x2 %0, %1, %2, %3;" : "=l"(d) : "l"(a), "l"(b), "l"(c));
    return d;
}
__device__ __forceinline__ ull bc2(float s) {
    ull r;
    asm("mov.b64 %0, {%1, %1};" : "=l"(r) : "r"(__float_as_uint(s)));
    return r;
}
__device__ __forceinline__ float2 unp(ull v) {
    unsigned lo, hi;
    asm("mov.b64 {%0, %1}, %2;" : "=r"(lo), "=r"(hi) : "l"(v));
    return make_float2(__uint_as_float(lo), __uint_as_float(hi));
}
__device__ __forceinline__ ull pk2(float a, float b) {
    ull r;
    asm("mov.b64 %0, {%1, %2};" : "=l"(r) : "r"(__float_as_uint(a)), "r"(__float_as_uint(b)));
    return r;
}
/* mma.sync m16n8k16 row.col f32.f16.f16.f32, accumulate in place */
__device__ __forceinline__ void mma16816(float& c0, float& c1, float& c2, float& c3,
                                         uint a0, uint a1, uint a2, uint a3,
                                         uint b0, uint b1) {
    asm volatile("mma.sync.aligned.m16n8k16.row.col.f32.f16.f16.f32 "
                 "{%0,%1,%2,%3}, {%4,%5,%6,%7}, {%8,%9}, {%0,%1,%2,%3};"
                 : "+f"(c0), "+f"(c1), "+f"(c2), "+f"(c3)
                 : "r"(a0), "r"(a1), "r"(a2), "r"(a3), "r"(b0), "r"(b1));
}

/* ------- prep: zero state + build fp16 conv-weight matrices --------------- */
__global__ void k_prepW(const float* __restrict__ tc1w,
                        const float* __restrict__ tc2w) {
    int tid = blockIdx.x * blockDim.x + threadIdx.x;
    int stride = gridDim.x * blockDim.x;
    for (int i = tid; i < NN; i += stride) { g_deg[i] = 0.f; g_cnt[i] = 0; }
    for (int i = tid; i < 128 * P1; i += stride) {
        int j = i / P1, k = i % P1;
        float v = 0.f;
        if (k < KD) {
            int t = k >> 6, ci = k & 63;
            int ot = j >> 6, co = j & 63;
            if (ot == 0) v = tc1w[(co * 64 + ci) * 3 + t];
            else if (t >= 1) v = tc1w[(co * 64 + ci) * 3 + (t - 1)];
        }
        g_B1h[i] = __float2half_rn(v);
    }
    for (int i = tid; i < 64 * P2; i += stride) {
        int j = i / P2, k = i % P2;
        float v = 0.f;
        if (k < 128) {
            int ot = k >> 6, co = k & 63;
            v = tc2w[(j * 64 + co) * 3 + ot];
        }
        g_B2h[i] = __float2half_rn(v);
    }
}

/* deg + slot-table fill in ONE pass (fixed stride, no prefix scan) */
__global__ void k_deg(const int* __restrict__ ei, const float* __restrict__ w) {
    int e = blockIdx.x * blockDim.x + threadIdx.x;
    pdl_wait();
    if (e >= EE) return;
    int s = ei[e], d = ei[EE + e];
    float wv = w[e];
    atomicAdd(&g_deg[d], wv);
    int p = atomicAdd(&g_cnt[d], 1);
    if (p < DSTR)
        g_edge[d * DSTR + p] = ((ull)__float_as_uint(wv) << 32) | (uint)s;
}

__global__ void k_dinv() {
    pdl_wait();
    int i = blockIdx.x * blockDim.x + threadIdx.x;
    if (i >= NN) return;
    float dv = rsqrtf(g_deg[i] + 1.0f);   /* self-loop weight 1 => deg>0 */
    g_dinv[i] = dv;
    g_self[i] = dv * dv;
}

/* ------- fused stage A: 2-wide agg of X + h1 = relu(A@W1+b1) -> fp16 ------ */
__global__ __launch_bounds__(128) void k_aggAH1(const float* __restrict__ X,
                                                const float* __restrict__ W1,
                                                const float* __restrict__ b1) {
    __shared__ __align__(16) uint4 sS[128][9];      /* staged rows, pad */
    __shared__ __align__(16) float sW1[128];
    __shared__ __align__(16) float sb1[64];
    int tid = threadIdx.x;
    if (tid < 128) sW1[tid] = W1[tid];      /* independent prologue */
    if (tid < 64)  sb1[tid] = b1[tid];
    __syncthreads();
    pdl_wait();                              /* before reading deg/dinv outputs */

    int blk0 = blockIdx.x * 128;
    int idx = blk0 + tid;
    {
        int b = idx & 7;
        int nt = idx >> 3;
        int n = nt % NN;
        int t = nt / NN;
        const float2* base = (const float2*)X + (size_t)(b * TT + T0 + t) * NN;
        float2 x = base[n];
        float sf = g_self[n];
        float dvd = g_dinv[n];
        float ax = sf * x.x, ay = sf * x.y;
        int cnt = g_cnt[n]; if (cnt > DSTR) cnt = DSTR;
        const ull* ep = g_edge + n * DSTR;
        int j = 0;
        for (; j + 2 <= cnt; j += 2) {
            ull e0 = ep[j], e1 = ep[j + 1];
            int s0 = (int)(e0 & 0xffffffffu);
            int s1 = (int)(e1 & 0xffffffffu);
            float w0v = __uint_as_float((uint)(e0 >> 32));
            float w1v = __uint_as_float((uint)(e1 >> 32));
            float2 xs0 = base[s0];
            float2 xs1 = base[s1];
            float nr0 = (g_dinv[s0] * w0v) * dvd;
            float nr1 = (g_dinv[s1] * w1v) * dvd;
            ax = fmaf(nr0, xs0.x, ax);
            ay = fmaf(nr0, xs0.y, ay);
            ax = fmaf(nr1, xs1.x, ax);
            ay = fmaf(nr1, xs1.y, ay);
        }
        if (j < cnt) {
            ull e = ep[j];
            int s = (int)(e & 0xffffffffu);
            float wv = __uint_as_float((uint)(e >> 32));
            float2 xs = base[s];
            float nr = (g_dinv[s] * wv) * dvd;
            ax = fmaf(nr, xs.x, ax);
            ay = fmaf(nr, xs.y, ay);
        }
        const float4* w0 = (const float4*)sW1;
        const float4* w1 = (const float4*)(sW1 + 64);
        const float4* bb = (const float4*)sb1;
#pragma unroll
        for (int q8 = 0; q8 < 8; q8++) {
            uint4 o;
            uint* op = (uint*)&o;
#pragma unroll
            for (int h = 0; h < 4; h++) {
                int q = q8 * 2 + (h >> 1);
                float4 W0 = w0[q], W1v = w1[q], Bv = bb[q];
                float v0, v1;
                if ((h & 1) == 0) {
                    v0 = fmaxf(fmaf(ax, W0.x, fmaf(ay, W1v.x, Bv.x)), 0.f);
                    v1 = fmaxf(fmaf(ax, W0.y, fmaf(ay, W1v.y, Bv.y)), 0.f);
                } else {
                    v0 = fmaxf(fmaf(ax, W0.z, fmaf(ay, W1v.z, Bv.z)), 0.f);
                    v1 = fmaxf(fmaf(ax, W0.w, fmaf(ay, W1v.w, Bv.w)), 0.f);
                }
                __half2 hh = __floats2half2_rn(v0, v1);
                op[h] = *(uint*)&hh;
            }
            sS[tid][q8] = o;
        }
    }
    __syncthreads();
    /* coalesced copy-out: block rows contiguous in g_h1h (8 uint4/row) */
    uint4* dst = g_h1h + (size_t)blk0 * 8;
    for (int i = tid; i < 128 * 8; i += 128) {
        int r = i >> 3, c = i & 7;
        dst[i] = sS[r][c];
    }
}

/* ------- fused: 64-wide fp16 gather agg + h2 = relu(C@W2+b2) -> fp16 ------ */
__device__ __forceinline__ void acc_row(const uint4* h1t, int s, int lane,
                                        float nr, float* aA, float* aB) {
    const uint4* rs = h1t + (size_t)s * 64 + lane;
    uint4 v0 = rs[0], v1 = rs[32];
    const __half2* p0 = (const __half2*)&v0;
    const __half2* p1 = (const __half2*)&v1;
#pragma unroll
    for (int k = 0; k < 4; k++) {
        float2 f0 = __half22float2(p0[k]);
        float2 f1 = __half22float2(p1[k]);
        aA[2 * k]     = fmaf(nr, f0.x, aA[2 * k]);
        aA[2 * k + 1] = fmaf(nr, f0.y, aA[2 * k + 1]);
        aB[2 * k]     = fmaf(nr, f1.x, aB[2 * k]);
        aB[2 * k + 1] = fmaf(nr, f1.y, aB[2 * k + 1]);
    }
}

__global__ __launch_bounds__(256) void k_aggCF1(const float* __restrict__ W2,
                                                const float* __restrict__ b2) {
    __shared__ float sC[64 * 65];          /* [r][ci] pad 65; reused for stores */
    __shared__ __align__(16) float sW2[4096];
    int tid = threadIdx.x;
    int t = blockIdx.y;
    for (int i = tid; i < 1024; i += 256)       /* independent prologue */
        ((float4*)sW2)[i] = ((const float4*)W2)[i];
    pdl_wait();                                  /* before reading h1/edges */

    int warp = tid >> 5, lane = tid & 31;
    int wi = blockIdx.x * 8 + warp;

    const uint4* h1t = g_h1h + (size_t)t * NN * 64;
    const uint4* rn = h1t + (size_t)wi * 64 + lane;
    float sf = g_self[wi];
    float dvd = g_dinv[wi];
    float aA[8], aB[8];
    {
        uint4 v0 = rn[0], v1 = rn[32];
        const __half2* p0 = (const __half2*)&v0;
        const __half2* p1 = (const __half2*)&v1;
#pragma unroll
        for (int k = 0; k < 4; k++) {
            float2 f0 = __half22float2(p0[k]);
            float2 f1 = __half22float2(p1[k]);
            aA[2 * k]     = sf * f0.x;
            aA[2 * k + 1] = sf * f0.y;
            aB[2 * k]     = sf * f1.x;
            aB[2 * k + 1] = sf * f1.y;
        }
    }
    int cnt = g_cnt[wi]; if (cnt > DSTR) cnt = DSTR;
    const ull* ep = g_edge + wi * DSTR;
    int j = 0;
    for (; j + 2 <= cnt; j += 2) {
        ull e0 = ep[j], e1 = ep[j + 1];
        int s0 = (int)(e0 & 0xffffffffu);
        int s1 = (int)(e1 & 0xffffffffu);
        float w0v = __uint_as_float((uint)(e0 >> 32));
        float w1v = __uint_as_float((uint)(e1 >> 32));
        const uint4* rs0 = h1t + (size_t)s0 * 64 + lane;
        const uint4* rs1 = h1t + (size_t)s1 * 64 + lane;
        float nr0 = (g_dinv[s0] * w0v) * dvd;
        float nr1 = (g_dinv[s1] * w1v) * dvd;
        uint4 a0 = rs0[0], a1 = rs0[32];
        uint4 b0 = rs1[0], b1 = rs1[32];
        {
            const __half2* p0 = (const __half2*)&a0;
            const __half2* p1 = (const __half2*)&a1;
            const __half2* q0 = (const __half2*)&b0;
            const __half2* q1 = (const __half2*)&b1;
#pragma unroll
            for (int k = 0; k < 4; k++) {
                float2 f0 = __half22float2(p0[k]);
                float2 f1 = __half22float2(p1[k]);
                float2 g0 = __half22float2(q0[k]);
                float2 g1 = __half22float2(q1[k]);
                aA[2 * k]     = fmaf(nr0, f0.x, aA[2 * k]);
                aA[2 * k + 1] = fmaf(nr0, f0.y, aA[2 * k + 1]);
                aB[2 * k]     = fmaf(nr0, f1.x, aB[2 * k]);
                aB[2 * k + 1] = fmaf(nr0, f1.y, aB[2 * k + 1]);
                aA[2 * k]     = fmaf(nr1, g0.x, aA[2 * k]);
                aA[2 * k + 1] = fmaf(nr1, g0.y, aA[2 * k + 1]);
                aB[2 * k]     = fmaf(nr1, g1.x, aB[2 * k]);
                aB[2 * k + 1] = fmaf(nr1, g1.y, aB[2 * k + 1]);
            }
        }
    }
    if (j < cnt) {
        ull e = ep[j];
        int s = (int)(e & 0xffffffffu);
        float wv = __uint_as_float((uint)(e >> 32));
        float nr = (g_dinv[s] * wv) * dvd;
        acc_row(h1t, s, lane, nr, aA, aB);
    }
    {
        int bl = lane >> 3;
        int f0 = (lane & 7) * 8;
        float* pA = sC + (warp * 8 + bl) * 65 + f0;
        float* pB = sC + (warp * 8 + 4 + bl) * 65 + f0;
#pragma unroll
        for (int k = 0; k < 8; k++) { pA[k] = aA[k]; pB[k] = aB[k]; }
    }
    __syncthreads();

    int r2 = tid & 31, g = tid >> 5;
    ull accA[4], accB[4];
#pragma unroll
    for (int k = 0; k < 4; k++) {
        float2 bbv = __ldg((const float2*)b2 + g * 4 + k);
        accA[k] = pk2(bbv.x, bbv.y);
        accB[k] = accA[k];
    }
    const float* cA = sC + r2 * 65;
    const float* cB = sC + (r2 + 32) * 65;
#pragma unroll 4
    for (int ci = 0; ci < 64; ci++) {
        ull xA = bc2(cA[ci]);
        ull xB = bc2(cB[ci]);
        const ulonglong2* wp = (const ulonglong2*)(sW2 + ci * 64 + g * 8);
        ulonglong2 wa = wp[0], wb = wp[1];
        accA[0] = fma2(xA, wa.x, accA[0]);
        accA[1] = fma2(xA, wa.y, accA[1]);
        accA[2] = fma2(xA, wb.x, accA[2]);
        accA[3] = fma2(xA, wb.y, accA[3]);
        accB[0] = fma2(xB, wa.x, accB[0]);
        accB[1] = fma2(xB, wa.y, accB[1]);
        accB[2] = fma2(xB, wb.x, accB[2]);
        accB[3] = fma2(xB, wb.y, accB[3]);
    }
    __syncthreads();   /* all GEMM reads of sC done; reuse as half buffer */

    /* stage results as half into sC: [64 rows][pitch 66 halves] */
    __half* sH = (__half*)sC;
#pragma unroll
    for (int k = 0; k < 4; k++) {
        int col = g * 8 + 2 * k;
        float2 u = unp(accA[k]);
        float2 v = unp(accB[k]);
        *(__half2*)(sH + r2 * 66 + col) =
            __floats2half2_rn(fmaxf(u.x, 0.f), fmaxf(u.y, 0.f));
        *(__half2*)(sH + (r2 + 32) * 66 + col) =
            __floats2half2_rn(fmaxf(v.x, 0.f), fmaxf(v.y, 0.f));
    }
    __syncthreads();

    /* coalesced copy-out: 64 rows x 32 uints each */
    size_t nb0 = (size_t)blockIdx.x * 64;
    const uint* sU = (const uint*)sC;
    for (int i = tid; i < 2048; i += 256) {
        int r = i >> 5, cu = i & 31;
        uint v = sU[r * 33 + cu];
        ((uint*)g_h2h)[(nb0 + r) * (KD / 2) + t * 32 + cu] = v;
    }
}

/* ---------------- F2: tensor-core temporal convs + head ------------------- */
#define F2_SMEM (128*P1*2 + 128*P1*2 + 128*P2*2 + 64*P2*2 + (128+64+64)*4)
__global__ __launch_bounds__(256, 1) void k_f2(const float* __restrict__ tc1b,
                                               const float* __restrict__ tc2b,
                                               const float* __restrict__ ow,
                                               const float* __restrict__ ob,
                                               float* __restrict__ out) {
    extern __shared__ __align__(16) char smraw[];
    __half* A_s  = (__half*)smraw;                       /* [128][P1] */
    __half* B1t  = A_s + 128 * P1;                       /* [128][P1] */
    __half* A2   = B1t + 128 * P1;                       /* [128][P2] */
    __half* B2t  = A2 + 128 * P2;                        /* [64][P2]  */
    float*  sb1f = (float*)(B2t + 64 * P2);              /* [128] */
    float*  sb2f = sb1f + 128;                           /* [64] */
    float*  ows  = sb2f + 64;                            /* [64] */

    int tid = threadIdx.x;
    int blk = blockIdx.x;

    /* independent prologue: weights + biases (prepW transitively complete) */
    {
        const uint4* s1 = (const uint4*)g_B1h;
        uint4* d1 = (uint4*)B1t;
        for (int i = tid; i < 128 * P1 / 8; i += 256) d1[i] = s1[i];
        const uint4* s2 = (const uint4*)g_B2h;
        uint4* d2 = (uint4*)B2t;
        for (int i = tid; i < 64 * P2 / 8; i += 256) d2[i] = s2[i];
    }
    if (tid < 128) sb1f[tid] = tc1b[tid & 63];
    else if (tid < 192) sb2f[tid - 128] = tc2b[tid - 128];
    else if (tid < 256) ows[tid - 192] = ow[tid - 192];
    pdl_wait();                       /* before reading g_h2h */
    {
        const uint4* src = (const uint4*)(g_h2h + (size_t)blk * 128 * KD);
        for (int i = tid; i < 128 * 24; i += 256) {
            int r = i / 24, c = i % 24;
            ((uint4*)(A_s + r * P1))[c] = src[i];
        }
    }
    __syncthreads();

    int warp = tid >> 5, lane = tid & 31;
    int g = lane >> 2, tc = lane & 3;
    int m0 = warp * 16;
    int rA = (m0 + g) * P1, rA8 = (m0 + g + 8) * P1;

    float c1[16][4];
#pragma unroll
    for (int nt = 0; nt < 16; nt++) {
        float bb0 = sb1f[nt * 8 + 2 * tc];
        float bb1 = sb1f[nt * 8 + 2 * tc + 1];
        c1[nt][0] = bb0; c1[nt][1] = bb1; c1[nt][2] = bb0; c1[nt][3] = bb1;
    }
#pragma unroll
    for (int k0 = 0; k0 < 12; k0++) {
        int kc = k0 * 16 + 2 * tc;
        uint a0 = *(const uint*)(A_s + rA + kc);
        uint a1 = *(const uint*)(A_s + rA8 + kc);
        uint a2 = *(const uint*)(A_s + rA + kc + 8);
        uint a3 = *(const uint*)(A_s + rA8 + kc + 8);
#pragma unroll
        for (int nt = 0; nt < 16; nt++) {
            const __half* bp = B1t + (nt * 8 + g) * P1 + kc;
            uint b0 = *(const uint*)bp;
            uint b1 = *(const uint*)(bp + 8);
            mma16816(c1[nt][0], c1[nt][1], c1[nt][2], c1[nt][3],
                     a0, a1, a2, a3, b0, b1);
        }
    }
    {
        __half* w0 = A2 + (m0 + g) * P2;
        __half* w8 = A2 + (m0 + g + 8) * P2;
#pragma unroll
        for (int nt = 0; nt < 16; nt++) {
            int col = nt * 8 + 2 * tc;
            *(__half2*)(w0 + col) = __floats2half2_rn(fmaxf(c1[nt][0], 0.f),
                                                      fmaxf(c1[nt][1], 0.f));
            *(__half2*)(w8 + col) = __floats2half2_rn(fmaxf(c1[nt][2], 0.f),
                                                      fmaxf(c1[nt][3], 0.f));
        }
    }
    __syncwarp();

    float c2[8][4];
#pragma unroll
    for (int nt = 0; nt < 8; nt++) {
        float bb0 = sb2f[nt * 8 + 2 * tc];
        float bb1 = sb2f[nt * 8 + 2 * tc + 1];
        c2[nt][0] = bb0; c2[nt][1] = bb1; c2[nt][2] = bb0; c2[nt][3] = bb1;
    }
    int r2A = (m0 + g) * P2, r2A8 = (m0 + g + 8) * P2;
#pragma unroll
    for (int k0 = 0; k0 < 8; k0++) {
        int kc = k0 * 16 + 2 * tc;
        uint a0 = *(const uint*)(A2 + r2A + kc);
        uint a1 = *(const uint*)(A2 + r2A8 + kc);
        uint a2 = *(const uint*)(A2 + r2A + kc + 8);
        uint a3 = *(const uint*)(A2 + r2A8 + kc + 8);
#pragma unroll
        for (int nt = 0; nt < 8; nt++) {
            const __half* bp = B2t + (nt * 8 + g) * P2 + kc;
            uint b0 = *(const uint*)bp;
            uint b1 = *(const uint*)(bp + 8);
            mma16816(c2[nt][0], c2[nt][1], c2[nt][2], c2[nt][3],
                     a0, a1, a2, a3, b0, b1);
        }
    }
    float accR = 0.f, accR8 = 0.f;
#pragma unroll
    for (int nt = 0; nt < 8; nt++) {
        int col = nt * 8 + 2 * tc;
        float w0 = ows[col], w1 = ows[col + 1];
        accR  = fmaf(fmaxf(c2[nt][0], 0.f), w0, accR);
        accR  = fmaf(fmaxf(c2[nt][1], 0.f), w1, accR);
        accR8 = fmaf(fmaxf(c2[nt][2], 0.f), w0, accR8);
        accR8 = fmaf(fmaxf(c2[nt][3], 0.f), w1, accR8);
    }
    accR  += __shfl_xor_sync(0xffffffffu, accR, 1);
    accR  += __shfl_xor_sync(0xffffffffu, accR, 2);
    accR8 += __shfl_xor_sync(0xffffffffu, accR8, 1);
    accR8 += __shfl_xor_sync(0xffffffffu, accR8, 2);
    if (tc == 0) {
        float ob0 = __ldg(ob);
        int nb1 = blk * 128 + m0 + g;
        int nb2 = nb1 + 8;
        out[(nb1 & 7) * NN + (nb1 >> 3)] = accR + ob0;
        out[(nb2 & 7) * NN + (nb2 >> 3)] = accR8 + ob0;
    }
}

/* ---------------- launch helpers ---------------- */
template <typename F, typename... A>
static void lp(F f, dim3 g, dim3 b, size_t sm, bool pdl, A... args) {
    cudaLaunchConfig_t cfg = {};
    cfg.gridDim = g;
    cfg.blockDim = b;
    cfg.dynamicSmemBytes = sm;
    cfg.stream = 0;
    cudaLaunchAttribute attr[1];
    if (pdl) {
        attr[0].id = cudaLaunchAttributeProgrammaticStreamSerialization;
        attr[0].val.programmaticStreamSerializationAllowed = 1;
        cfg.attrs = attr;
        cfg.numAttrs = 1;
    }
    cudaError_t e = cudaLaunchKernelEx(&cfg, f, args...);
    if (e != cudaSuccess) {
        f<<<g, b, sm>>>(args...);   /* fallback: plain serialized launch */
    }
}

extern "C" void kernel_launch(void* const* d_in, const int* in_sizes, int n_in,
                              void* d_out, int out_size) {
    const float* X    = (const float*)d_in[0];
    const int*   ei   = (const int*)d_in[1];
    const float* ew   = (const float*)d_in[2];
    const float* W1   = (const float*)d_in[3];
    const float* b1   = (const float*)d_in[4];
    const float* W2   = (const float*)d_in[5];
    const float* b2   = (const float*)d_in[6];
    const float* tc1w = (const float*)d_in[7];
    const float* tc1b = (const float*)d_in[8];
    const float* tc2w = (const float*)d_in[9];
    const float* tc2b = (const float*)d_in[10];
    const float* ow   = (const float*)d_in[11];
    const float* ob   = (const float*)d_in[12];
    float* out = (float*)d_out;

    cudaFuncSetAttribute(k_f2, cudaFuncAttributeMaxDynamicSharedMemorySize, F2_SMEM);

    lp(k_prepW,  dim3(32), dim3(256), 0, false, tc1w, tc2w);
    lp(k_deg,    dim3((EE + 255) / 256), dim3(256), 0, true, ei, ew);
    lp(k_dinv,   dim3((NN + 255) / 256), dim3(256), 0, true);
    lp(k_aggAH1, dim3(ROWS / 128), dim3(128), 0, true, X, W1, b1);
    lp(k_aggCF1, dim3(NN / 8, TS), dim3(256), 0, true, W2, b2);
    lp(k_f2,     dim3(NB / 128), dim3(256), F2_SMEM, true, tc1b, tc2b, ow, ob, out);
}

// round 16
// speedup vs baseline: 1.0324x; 1.0324x over previous
#include <cuda_runtime.h>
#include <cuda_fp16.h>

#define NN 10000
#define EE 160000
#define BB 8
#define TT 12
#define HH 64
#define TS 3
#define T0 9
#define ROWS (TS*NN*BB)   /* 240000 rows of 64 features */
#define NB  (BB*NN)       /* 80000 (n,b) rows */
#define KD  192           /* stage1 K = 3t * 64ci */
#define P1  200           /* smem pitch (halves) for K=192 tiles */
#define P2  136           /* smem pitch for K=128 tiles */
#define DSTR 64           /* fixed edge-table stride per node */

typedef unsigned long long ull;
typedef unsigned int uint;

/* ---------------- device scratch (no allocs allowed) ---------------- */
__device__ float  g_deg[NN];
__device__ float  g_dinv[NN];
__device__ int    g_cnt[NN];
__device__ float2 g_Xs[BB * TS * NN];   /* dinv-prescaled X, [b][t][n], 1.9MB */
__device__ ull    g_edge[NN * DSTR];    /* packed (src low, w high), slot table */
__device__ uint4  g_h1h[TS * NN * 64];  /* fp16 h1' (dinv-prescaled) 30.7MB */
__device__ __half g_h2h[(size_t)NB * KD];  /* fp16 h2: [nb][t*64+ci] 30.7MB */
__device__ __half g_B1h[128 * P1];      /* stage1 weights B^T padded */
__device__ __half g_B2h[64 * P2];       /* stage2 weights B^T padded */

/* ---------------- PDL ---------------- */
__device__ __forceinline__ void pdl_wait() {
    asm volatile("griddepcontrol.wait;" ::: "memory");
}

/* ---------------- packed f32x2 helpers ---------------- */
__device__ __forceinline__ ull fma2(ull a, ull b, ull c) {
    ull d;
    asm("fma.rn.f32x2 %0, %1, %2, %3;" : "=l"(d) : "l"(a), "l"(b), "l"(c));
    return d;
}
__device__ __forceinline__ ull bc2(float s) {
    ull r;
    asm("mov.b64 %0, {%1, %1};" : "=l"(r) : "r"(__float_as_uint(s)));
    return r;
}
__device__ __forceinline__ float2 unp(ull v) {
    unsigned lo, hi;
    asm("mov.b64 {%0, %1}, %2;" : "=r"(lo), "=r"(hi) : "l"(v));
    return make_float2(__uint_as_float(lo), __uint_as_float(hi));
}
__device__ __forceinline__ ull pk2(float a, float b) {
    ull r;
    asm("mov.b64 %0, {%1, %2};" : "=l"(r) : "r"(__float_as_uint(a)), "r"(__float_as_uint(b)));
    return r;
}
/* mma.sync m16n8k16 row.col f32.f16.f16.f32, accumulate in place */
__device__ __forceinline__ void mma16816(float& c0, float& c1, float& c2, float& c3,
                                         uint a0, uint a1, uint a2, uint a3,
                                         uint b0, uint b1) {
    asm volatile("mma.sync.aligned.m16n8k16.row.col.f32.f16.f16.f32 "
                 "{%0,%1,%2,%3}, {%4,%5,%6,%7}, {%8,%9}, {%0,%1,%2,%3};"
                 : "+f"(c0), "+f"(c1), "+f"(c2), "+f"(c3)
                 : "r"(a0), "r"(a1), "r"(a2), "r"(a3), "r"(b0), "r"(b1));
}

/* ------- prep: zero state + build fp16 conv-weight matrices --------------- */
__global__ void k_prepW(const float* __restrict__ tc1w,
                        const float* __restrict__ tc2w) {
    int tid = blockIdx.x * blockDim.x + threadIdx.x;
    int stride = gridDim.x * blockDim.x;
    for (int i = tid; i < NN; i += stride) { g_deg[i] = 0.f; g_cnt[i] = 0; }
    for (int i = tid; i < 128 * P1; i += stride) {
        int j = i / P1, k = i % P1;
        float v = 0.f;
        if (k < KD) {
            int t = k >> 6, ci = k & 63;
            int ot = j >> 6, co = j & 63;
            if (ot == 0) v = tc1w[(co * 64 + ci) * 3 + t];
            else if (t >= 1) v = tc1w[(co * 64 + ci) * 3 + (t - 1)];
        }
        g_B1h[i] = __float2half_rn(v);
    }
    for (int i = tid; i < 64 * P2; i += stride) {
        int j = i / P2, k = i % P2;
        float v = 0.f;
        if (k < 128) {
            int ot = k >> 6, co = k & 63;
            v = tc2w[(j * 64 + co) * 3 + ot];
        }
        g_B2h[i] = __float2half_rn(v);
    }
}

/* deg + slot-table fill in ONE pass (fixed stride, no prefix scan) */
__global__ void k_deg(const int* __restrict__ ei, const float* __restrict__ w) {
    int e = blockIdx.x * blockDim.x + threadIdx.x;
    pdl_wait();
    if (e >= EE) return;
    int s = ei[e], d = ei[EE + e];
    float wv = w[e];
    atomicAdd(&g_deg[d], wv);
    int p = atomicAdd(&g_cnt[d], 1);
    if (p < DSTR)
        g_edge[d * DSTR + p] = ((ull)__float_as_uint(wv) << 32) | (uint)s;
}

/* dinv + prescaled X (Xs = dinv[n] * x[b,t,n]) */
__global__ void k_dinv(const float* __restrict__ X) {
    pdl_wait();
    int i = blockIdx.x * blockDim.x + threadIdx.x;
    if (i >= NN) return;
    float dv = rsqrtf(g_deg[i] + 1.0f);   /* self-loop weight 1 => deg>0 */
    g_dinv[i] = dv;
    const float2* xp = (const float2*)X;
#pragma unroll
    for (int b = 0; b < BB; b++)
#pragma unroll
        for (int t = 0; t < TS; t++) {
            float2 x = xp[(size_t)(b * TT + T0 + t) * NN + i];
            g_Xs[(b * TS + t) * NN + i] = make_float2(dv * x.x, dv * x.y);
        }
}

/* ------- fused stage A: agg of Xs (no per-edge dinv) + h1' -> fp16 -------- */
__global__ __launch_bounds__(128) void k_aggAH1(const float* __restrict__ W1,
                                                const float* __restrict__ b1) {
    __shared__ __align__(16) uint4 sS[128][9];      /* staged rows, pad */
    __shared__ __align__(16) float sW1[128];
    __shared__ __align__(16) float sb1[64];
    int tid = threadIdx.x;
    if (tid < 128) sW1[tid] = W1[tid];      /* independent prologue */
    if (tid < 64)  sb1[tid] = b1[tid];
    __syncthreads();
    pdl_wait();                              /* before reading deg/dinv/Xs */

    int blk0 = blockIdx.x * 128;
    int idx = blk0 + tid;
    {
        int b = idx & 7;
        int nt = idx >> 3;
        int n = nt % NN;
        int t = nt / NN;
        const float2* base = g_Xs + (size_t)(b * TS + t) * NN;
        float dvd = g_dinv[n];
        float2 xn = base[n];
        float ax = xn.x, ay = xn.y;          /* self term = Xs[n] */
        int cnt = g_cnt[n]; if (cnt > DSTR) cnt = DSTR;
        const ull* ep = g_edge + n * DSTR;
        int j = 0;
        for (; j + 4 <= cnt; j += 4) {
            ull e0 = ep[j], e1 = ep[j + 1], e2 = ep[j + 2], e3 = ep[j + 3];
            int s0 = (int)(e0 & 0xffffffffu);
            int s1 = (int)(e1 & 0xffffffffu);
            int s2 = (int)(e2 & 0xffffffffu);
            int s3 = (int)(e3 & 0xffffffffu);
            float2 x0 = base[s0], x1 = base[s1], x2 = base[s2], x3 = base[s3];
            float w0 = __uint_as_float((uint)(e0 >> 32));
            float w1 = __uint_as_float((uint)(e1 >> 32));
            float w2 = __uint_as_float((uint)(e2 >> 32));
            float w3 = __uint_as_float((uint)(e3 >> 32));
            ax = fmaf(w0, x0.x, ax); ay = fmaf(w0, x0.y, ay);
            ax = fmaf(w1, x1.x, ax); ay = fmaf(w1, x1.y, ay);
            ax = fmaf(w2, x2.x, ax); ay = fmaf(w2, x2.y, ay);
            ax = fmaf(w3, x3.x, ax); ay = fmaf(w3, x3.y, ay);
        }
        for (; j < cnt; j++) {
            ull e = ep[j];
            int s = (int)(e & 0xffffffffu);
            float wv = __uint_as_float((uint)(e >> 32));
            float2 xs = base[s];
            ax = fmaf(wv, xs.x, ax);
            ay = fmaf(wv, xs.y, ay);
        }
        ax *= dvd; ay *= dvd;                /* final dinv[d] scale */
        const float4* w0 = (const float4*)sW1;
        const float4* w1 = (const float4*)(sW1 + 64);
        const float4* bb = (const float4*)sb1;
#pragma unroll
        for (int q8 = 0; q8 < 8; q8++) {
            uint4 o;
            uint* op = (uint*)&o;
#pragma unroll
            for (int h = 0; h < 4; h++) {
                int q = q8 * 2 + (h >> 1);
                float4 W0 = w0[q], W1v = w1[q], Bv = bb[q];
                float v0, v1;
                if ((h & 1) == 0) {
                    v0 = fmaxf(fmaf(ax, W0.x, fmaf(ay, W1v.x, Bv.x)), 0.f);
                    v1 = fmaxf(fmaf(ax, W0.y, fmaf(ay, W1v.y, Bv.y)), 0.f);
                } else {
                    v0 = fmaxf(fmaf(ax, W0.z, fmaf(ay, W1v.z, Bv.z)), 0.f);
                    v1 = fmaxf(fmaf(ax, W0.w, fmaf(ay, W1v.w, Bv.w)), 0.f);
                }
                /* store h1' = dinv[n] * relu(h1): pre-scale for stage C */
                __half2 hh = __floats2half2_rn(dvd * v0, dvd * v1);
                op[h] = *(uint*)&hh;
            }
            sS[tid][q8] = o;
        }
    }
    __syncthreads();
    /* coalesced copy-out: block rows contiguous in g_h1h (8 uint4/row) */
    uint4* dst = g_h1h + (size_t)blk0 * 8;
    for (int i = tid; i < 128 * 8; i += 128) {
        int r = i >> 3, c = i & 7;
        dst[i] = sS[r][c];
    }
}

/* ------- fused: fp16 gather of h1' (no per-edge dinv) + W2 GEMM ----------- */
__device__ __forceinline__ void acc_row(const uint4* h1t, int s, int lane,
                                        float nr, float* aA, float* aB) {
    const uint4* rs = h1t + (size_t)s * 64 + lane;
    uint4 v0 = rs[0], v1 = rs[32];
    const __half2* p0 = (const __half2*)&v0;
    const __half2* p1 = (const __half2*)&v1;
#pragma unroll
    for (int k = 0; k < 4; k++) {
        float2 f0 = __half22float2(p0[k]);
        float2 f1 = __half22float2(p1[k]);
        aA[2 * k]     = fmaf(nr, f0.x, aA[2 * k]);
        aA[2 * k + 1] = fmaf(nr, f0.y, aA[2 * k + 1]);
        aB[2 * k]     = fmaf(nr, f1.x, aB[2 * k]);
        aB[2 * k + 1] = fmaf(nr, f1.y, aB[2 * k + 1]);
    }
}

__global__ __launch_bounds__(256) void k_aggCF1(const float* __restrict__ W2,
                                                const float* __restrict__ b2) {
    __shared__ float sC[64 * 65];          /* [r][ci] pad 65; reused for stores */
    __shared__ __align__(16) float sW2[4096];
    int tid = threadIdx.x;
    int t = blockIdx.y;
    for (int i = tid; i < 1024; i += 256)       /* independent prologue */
        ((float4*)sW2)[i] = ((const float4*)W2)[i];
    pdl_wait();                                  /* before reading h1/edges */

    int warp = tid >> 5, lane = tid & 31;
    int wi = blockIdx.x * 8 + warp;

    const uint4* h1t = g_h1h + (size_t)t * NN * 64;
    const uint4* rn = h1t + (size_t)wi * 64 + lane;
    float dvd = g_dinv[wi];
    float aA[8], aB[8];
    {
        /* self term = h1'[wi] (already dinv-scaled once) */
        uint4 v0 = rn[0], v1 = rn[32];
        const __half2* p0 = (const __half2*)&v0;
        const __half2* p1 = (const __half2*)&v1;
#pragma unroll
        for (int k = 0; k < 4; k++) {
            float2 f0 = __half22float2(p0[k]);
            float2 f1 = __half22float2(p1[k]);
            aA[2 * k]     = f0.x;
            aA[2 * k + 1] = f0.y;
            aB[2 * k]     = f1.x;
            aB[2 * k + 1] = f1.y;
        }
    }
    int cnt = g_cnt[wi]; if (cnt > DSTR) cnt = DSTR;
    const ull* ep = g_edge + wi * DSTR;
    int j = 0;
    for (; j + 2 <= cnt; j += 2) {
        ull e0 = ep[j], e1 = ep[j + 1];
        int s0 = (int)(e0 & 0xffffffffu);
        int s1 = (int)(e1 & 0xffffffffu);
        float w0v = __uint_as_float((uint)(e0 >> 32));
        float w1v = __uint_as_float((uint)(e1 >> 32));
        const uint4* rs0 = h1t + (size_t)s0 * 64 + lane;
        const uint4* rs1 = h1t + (size_t)s1 * 64 + lane;
        uint4 a0 = rs0[0], a1 = rs0[32];
        uint4 b0 = rs1[0], b1 = rs1[32];
        {
            const __half2* p0 = (const __half2*)&a0;
            const __half2* p1 = (const __half2*)&a1;
            const __half2* q0 = (const __half2*)&b0;
            const __half2* q1 = (const __half2*)&b1;
#pragma unroll
            for (int k = 0; k < 4; k++) {
                float2 f0 = __half22float2(p0[k]);
                float2 f1 = __half22float2(p1[k]);
                float2 g0 = __half22float2(q0[k]);
                float2 g1 = __half22float2(q1[k]);
                aA[2 * k]     = fmaf(w0v, f0.x, aA[2 * k]);
                aA[2 * k + 1] = fmaf(w0v, f0.y, aA[2 * k + 1]);
                aB[2 * k]     = fmaf(w0v, f1.x, aB[2 * k]);
                aB[2 * k + 1] = fmaf(w0v, f1.y, aB[2 * k + 1]);
                aA[2 * k]     = fmaf(w1v, g0.x, aA[2 * k]);
                aA[2 * k + 1] = fmaf(w1v, g0.y, aA[2 * k + 1]);
                aB[2 * k]     = fmaf(w1v, g1.x, aB[2 * k]);
                aB[2 * k + 1] = fmaf(w1v, g1.y, aB[2 * k + 1]);
            }
        }
    }
    if (j < cnt) {
        ull e = ep[j];
        int s = (int)(e & 0xffffffffu);
        float wv = __uint_as_float((uint)(e >> 32));
        acc_row(h1t, s, lane, wv, aA, aB);
    }
    /* final dinv[d] scale, then stage */
    {
        int bl = lane >> 3;
        int f0 = (lane & 7) * 8;
        float* pA = sC + (warp * 8 + bl) * 65 + f0;
        float* pB = sC + (warp * 8 + 4 + bl) * 65 + f0;
#pragma unroll
        for (int k = 0; k < 8; k++) { pA[k] = dvd * aA[k]; pB[k] = dvd * aB[k]; }
    }
    __syncthreads();

    int r2 = tid & 31, g = tid >> 5;
    ull accA[4], accB[4];
#pragma unroll
    for (int k = 0; k < 4; k++) {
        float2 bbv = __ldg((const float2*)b2 + g * 4 + k);
        accA[k] = pk2(bbv.x, bbv.y);
        accB[k] = accA[k];
    }
    const float* cA = sC + r2 * 65;
    const float* cB = sC + (r2 + 32) * 65;
#pragma unroll 4
    for (int ci = 0; ci < 64; ci++) {
        ull xA = bc2(cA[ci]);
        ull xB = bc2(cB[ci]);
        const ulonglong2* wp = (const ulonglong2*)(sW2 + ci * 64 + g * 8);
        ulonglong2 wa = wp[0], wb = wp[1];
        accA[0] = fma2(xA, wa.x, accA[0]);
        accA[1] = fma2(xA, wa.y, accA[1]);
        accA[2] = fma2(xA, wb.x, accA[2]);
        accA[3] = fma2(xA, wb.y, accA[3]);
        accB[0] = fma2(xB, wa.x, accB[0]);
        accB[1] = fma2(xB, wa.y, accB[1]);
        accB[2] = fma2(xB, wb.x, accB[2]);
        accB[3] = fma2(xB, wb.y, accB[3]);
    }
    __syncthreads();   /* all GEMM reads of sC done; reuse as half buffer */

    /* stage results as half into sC: [64 rows][pitch 66 halves] */
    __half* sH = (__half*)sC;
#pragma unroll
    for (int k = 0; k < 4; k++) {
        int col = g * 8 + 2 * k;
        float2 u = unp(accA[k]);
        float2 v = unp(accB[k]);
        *(__half2*)(sH + r2 * 66 + col) =
            __floats2half2_rn(fmaxf(u.x, 0.f), fmaxf(u.y, 0.f));
        *(__half2*)(sH + (r2 + 32) * 66 + col) =
            __floats2half2_rn(fmaxf(v.x, 0.f), fmaxf(v.y, 0.f));
    }
    __syncthreads();

    /* coalesced copy-out: 64 rows x 32 uints each */
    size_t nb0 = (size_t)blockIdx.x * 64;
    const uint* sU = (const uint*)sC;
    for (int i = tid; i < 2048; i += 256) {
        int r = i >> 5, cu = i & 31;
        uint v = sU[r * 33 + cu];
        ((uint*)g_h2h)[(nb0 + r) * (KD / 2) + t * 32 + cu] = v;
    }
}

/* ---------------- F2: tensor-core temporal convs + head ------------------- */
#define F2_SMEM (128*P1*2 + 128*P1*2 + 128*P2*2 + 64*P2*2 + (128+64+64)*4)
__global__ __launch_bounds__(256, 1) void k_f2(const float* __restrict__ tc1b,
                                               const float* __restrict__ tc2b,
                                               const float* __restrict__ ow,
                                               const float* __restrict__ ob,
                                               float* __restrict__ out) {
    extern __shared__ __align__(16) char smraw[];
    __half* A_s  = (__half*)smraw;                       /* [128][P1] */
    __half* B1t  = A_s + 128 * P1;                       /* [128][P1] */
    __half* A2   = B1t + 128 * P1;                       /* [128][P2] */
    __half* B2t  = A2 + 128 * P2;                        /* [64][P2]  */
    float*  sb1f = (float*)(B2t + 64 * P2);              /* [128] */
    float*  sb2f = sb1f + 128;                           /* [64] */
    float*  ows  = sb2f + 64;                            /* [64] */

    int tid = threadIdx.x;
    int blk = blockIdx.x;

    /* independent prologue: weights + biases (prepW transitively complete) */
    {
        const uint4* s1 = (const uint4*)g_B1h;
        uint4* d1 = (uint4*)B1t;
        for (int i = tid; i < 128 * P1 / 8; i += 256) d1[i] = s1[i];
        const uint4* s2 = (const uint4*)g_B2h;
        uint4* d2 = (uint4*)B2t;
        for (int i = tid; i < 64 * P2 / 8; i += 256) d2[i] = s2[i];
    }
    if (tid < 128) sb1f[tid] = tc1b[tid & 63];
    else if (tid < 192) sb2f[tid - 128] = tc2b[tid - 128];
    else if (tid < 256) ows[tid - 192] = ow[tid - 192];
    pdl_wait();                       /* before reading g_h2h */
    {
        const uint4* src = (const uint4*)(g_h2h + (size_t)blk * 128 * KD);
        for (int i = tid; i < 128 * 24; i += 256) {
            int r = i / 24, c = i % 24;
            ((uint4*)(A_s + r * P1))[c] = src[i];
        }
    }
    __syncthreads();

    int warp = tid >> 5, lane = tid & 31;
    int g = lane >> 2, tc = lane & 3;
    int m0 = warp * 16;
    int rA = (m0 + g) * P1, rA8 = (m0 + g + 8) * P1;

    float c1[16][4];
#pragma unroll
    for (int nt = 0; nt < 16; nt++) {
        float bb0 = sb1f[nt * 8 + 2 * tc];
        float bb1 = sb1f[nt * 8 + 2 * tc + 1];
        c1[nt][0] = bb0; c1[nt][1] = bb1; c1[nt][2] = bb0; c1[nt][3] = bb1;
    }
#pragma unroll
    for (int k0 = 0; k0 < 12; k0++) {
        int kc = k0 * 16 + 2 * tc;
        uint a0 = *(const uint*)(A_s + rA + kc);
        uint a1 = *(const uint*)(A_s + rA8 + kc);
        uint a2 = *(const uint*)(A_s + rA + kc + 8);
        uint a3 = *(const uint*)(A_s + rA8 + kc + 8);
#pragma unroll
        for (int nt = 0; nt < 16; nt++) {
            const __half* bp = B1t + (nt * 8 + g) * P1 + kc;
            uint b0 = *(const uint*)bp;
            uint b1 = *(const uint*)(bp + 8);
            mma16816(c1[nt][0], c1[nt][1], c1[nt][2], c1[nt][3],
                     a0, a1, a2, a3, b0, b1);
        }
    }
    {
        __half* w0 = A2 + (m0 + g) * P2;
        __half* w8 = A2 + (m0 + g + 8) * P2;
#pragma unroll
        for (int nt = 0; nt < 16; nt++) {
            int col = nt * 8 + 2 * tc;
            *(__half2*)(w0 + col) = __floats2half2_rn(fmaxf(c1[nt][0], 0.f),
                                                      fmaxf(c1[nt][1], 0.f));
            *(__half2*)(w8 + col) = __floats2half2_rn(fmaxf(c1[nt][2], 0.f),
                                                      fmaxf(c1[nt][3], 0.f));
        }
    }
    __syncwarp();

    float c2[8][4];
#pragma unroll
    for (int nt = 0; nt < 8; nt++) {
        float bb0 = sb2f[nt * 8 + 2 * tc];
        float bb1 = sb2f[nt * 8 + 2 * tc + 1];
        c2[nt][0] = bb0; c2[nt][1] = bb1; c2[nt][2] = bb0; c2[nt][3] = bb1;
    }
    int r2A = (m0 + g) * P2, r2A8 = (m0 + g + 8) * P2;
#pragma unroll
    for (int k0 = 0; k0 < 8; k0++) {
        int kc = k0 * 16 + 2 * tc;
        uint a0 = *(const uint*)(A2 + r2A + kc);
        uint a1 = *(const uint*)(A2 + r2A8 + kc);
        uint a2 = *(const uint*)(A2 + r2A + kc + 8);
        uint a3 = *(const uint*)(A2 + r2A8 + kc + 8);
#pragma unroll
        for (int nt = 0; nt < 8; nt++) {
            const __half* bp = B2t + (nt * 8 + g) * P2 + kc;
            uint b0 = *(const uint*)bp;
            uint b1 = *(const uint*)(bp + 8);
            mma16816(c2[nt][0], c2[nt][1], c2[nt][2], c2[nt][3],
                     a0, a1, a2, a3, b0, b1);
        }
    }
    float accR = 0.f, accR8 = 0.f;
#pragma unroll
    for (int nt = 0; nt < 8; nt++) {
        int col = nt * 8 + 2 * tc;
        float w0 = ows[col], w1 = ows[col + 1];
        accR  = fmaf(fmaxf(c2[nt][0], 0.f), w0, accR);
        accR  = fmaf(fmaxf(c2[nt][1], 0.f), w1, accR);
        accR8 = fmaf(fmaxf(c2[nt][2], 0.f), w0, accR8);
        accR8 = fmaf(fmaxf(c2[nt][3], 0.f), w1, accR8);
    }
    accR  += __shfl_xor_sync(0xffffffffu, accR, 1);
    accR  += __shfl_xor_sync(0xffffffffu, accR, 2);
    accR8 += __shfl_xor_sync(0xffffffffu, accR8, 1);
    accR8 += __shfl_xor_sync(0xffffffffu, accR8, 2);
    if (tc == 0) {
        float ob0 = __ldg(ob);
        int nb1 = blk * 128 + m0 + g;
        int nb2 = nb1 + 8;
        out[(nb1 & 7) * NN + (nb1 >> 3)] = accR + ob0;
        out[(nb2 & 7) * NN + (nb2 >> 3)] = accR8 + ob0;
    }
}

/* ---------------- launch helpers ---------------- */
template <typename F, typename... A>
static void lp(F f, dim3 g, dim3 b, size_t sm, bool pdl, A... args) {
    cudaLaunchConfig_t cfg = {};
    cfg.gridDim = g;
    cfg.blockDim = b;
    cfg.dynamicSmemBytes = sm;
    cfg.stream = 0;
    cudaLaunchAttribute attr[1];
    if (pdl) {
        attr[0].id = cudaLaunchAttributeProgrammaticStreamSerialization;
        attr[0].val.programmaticStreamSerializationAllowed = 1;
        cfg.attrs = attr;
        cfg.numAttrs = 1;
    }
    cudaError_t e = cudaLaunchKernelEx(&cfg, f, args...);
    if (e != cudaSuccess) {
        f<<<g, b, sm>>>(args...);   /* fallback: plain serialized launch */
    }
}

extern "C" void kernel_launch(void* const* d_in, const int* in_sizes, int n_in,
                              void* d_out, int out_size) {
    const float* X    = (const float*)d_in[0];
    const int*   ei   = (const int*)d_in[1];
    const float* ew   = (const float*)d_in[2];
    const float* W1   = (const float*)d_in[3];
    const float* b1   = (const float*)d_in[4];
    const float* W2   = (const float*)d_in[5];
    const float* b2   = (const float*)d_in[6];
    const float* tc1w = (const float*)d_in[7];
    const float* tc1b = (const float*)d_in[8];
    const float* tc2w = (const float*)d_in[9];
    const float* tc2b = (const float*)d_in[10];
    const float* ow   = (const float*)d_in[11];
    const float* ob   = (const float*)d_in[12];
    float* out = (float*)d_out;

    cudaFuncSetAttribute(k_f2, cudaFuncAttributeMaxDynamicSharedMemorySize, F2_SMEM);

    lp(k_prepW,  dim3(32), dim3(256), 0, false, tc1w, tc2w);
    lp(k_deg,    dim3((EE + 255) / 256), dim3(256), 0, true, ei, ew);
    lp(k_dinv,   dim3((NN + 255) / 256), dim3(256), 0, true, X);
    lp(k_aggAH1, dim3(ROWS / 128), dim3(128), 0, true, W1, b1);
    lp(k_aggCF1, dim3(NN / 8, TS), dim3(256), 0, true, W2, b2);
    lp(k_f2,     dim3(NB / 128), dim3(256), F2_SMEM, true, tc1b, tc2b, ow, ob, out);
}

// round 17
// speedup vs baseline: 1.1591x; 1.1227x over previous
#include <cuda_runtime.h>
#include <cuda_fp16.h>

#define NN 10000
#define EE 160000
#define BB 8
#define TT 12
#define HH 64
#define TS 3
#define T0 9
#define ROWS (TS*NN*BB)   /* 240000 rows of 64 features */
#define NB  (BB*NN)       /* 80000 (n,b) rows */
#define KD  192           /* stage1 K = 3t * 64ci */
#define P1  200           /* smem pitch (halves) for K=192 tiles */
#define P2  136           /* smem pitch for K=128 tiles */
#define DSTR 64           /* fixed edge-table stride per node */

typedef unsigned long long ull;
typedef unsigned int uint;

/* ---------------- device scratch (no allocs allowed) ---------------- */
__device__ float  g_deg[NN];
__device__ float  g_dinv[NN];
__device__ int    g_cnt[NN];
__device__ float2 g_Xs[TS * NN * BB];   /* dinv-prescaled X, [t][n][b], 1.9MB */
__device__ ull    g_edge[NN * DSTR];    /* packed (src low, w high), slot table */
__device__ uint4  g_h1h[TS * NN * 64];  /* fp16 h1' (dinv-prescaled) 30.7MB */
__device__ __half g_h2h[(size_t)NB * KD];  /* fp16 h2: [nb][t*64+ci] 30.7MB */
__device__ __half g_B1h[128 * P1];      /* stage1 weights B^T padded */
__device__ __half g_B2h[64 * P2];       /* stage2 weights B^T padded */

/* ---------------- PDL ---------------- */
__device__ __forceinline__ void pdl_wait() {
    asm volatile("griddepcontrol.wait;" ::: "memory");
}

/* ---------------- packed f32x2 helpers ---------------- */
__device__ __forceinline__ ull fma2(ull a, ull b, ull c) {
    ull d;
    asm("fma.rn.f32x2 %0, %1, %2, %3;" : "=l"(d) : "l"(a), "l"(b), "l"(c));
    return d;
}
__device__ __forceinline__ ull bc2(float s) {
    ull r;
    asm("mov.b64 %0, {%1, %1};" : "=l"(r) : "r"(__float_as_uint(s)));
    return r;
}
__device__ __forceinline__ float2 unp(ull v) {
    unsigned lo, hi;
    asm("mov.b64 {%0, %1}, %2;" : "=r"(lo), "=r"(hi) : "l"(v));
    return make_float2(__uint_as_float(lo), __uint_as_float(hi));
}
__device__ __forceinline__ ull pk2(float a, float b) {
    ull r;
    asm("mov.b64 %0, {%1, %2};" : "=l"(r) : "r"(__float_as_uint(a)), "r"(__float_as_uint(b)));
    return r;
}
/* mma.sync m16n8k16 row.col f32.f16.f16.f32, accumulate in place */
__device__ __forceinline__ void mma16816(float& c0, float& c1, float& c2, float& c3,
                                         uint a0, uint a1, uint a2, uint a3,
                                         uint b0, uint b1) {
    asm volatile("mma.sync.aligned.m16n8k16.row.col.f32.f16.f16.f32 "
                 "{%0,%1,%2,%3}, {%4,%5,%6,%7}, {%8,%9}, {%0,%1,%2,%3};"
                 : "+f"(c0), "+f"(c1), "+f"(c2), "+f"(c3)
                 : "r"(a0), "r"(a1), "r"(a2), "r"(a3), "r"(b0), "r"(b1));
}

/* ------- prep: zero state + build fp16 conv-weight matrices --------------- */
__global__ void k_prepW(const float* __restrict__ tc1w,
                        const float* __restrict__ tc2w) {
    int tid = blockIdx.x * blockDim.x + threadIdx.x;
    int stride = gridDim.x * blockDim.x;
    for (int i = tid; i < NN; i += stride) { g_deg[i] = 0.f; g_cnt[i] = 0; }
    for (int i = tid; i < 128 * P1; i += stride) {
        int j = i / P1, k = i % P1;
        float v = 0.f;
        if (k < KD) {
            int t = k >> 6, ci = k & 63;
            int ot = j >> 6, co = j & 63;
            if (ot == 0) v = tc1w[(co * 64 + ci) * 3 + t];
            else if (t >= 1) v = tc1w[(co * 64 + ci) * 3 + (t - 1)];
        }
        g_B1h[i] = __float2half_rn(v);
    }
    for (int i = tid; i < 64 * P2; i += stride) {
        int j = i / P2, k = i % P2;
        float v = 0.f;
        if (k < 128) {
            int ot = k >> 6, co = k & 63;
            v = tc2w[(j * 64 + co) * 3 + ot];
        }
        g_B2h[i] = __float2half_rn(v);
    }
}

/* deg + slot-table fill in ONE pass (fixed stride, no prefix scan) */
__global__ void k_deg(const int* __restrict__ ei, const float* __restrict__ w) {
    int e = blockIdx.x * blockDim.x + threadIdx.x;
    pdl_wait();
    if (e >= EE) return;
    int s = ei[e], d = ei[EE + e];
    float wv = w[e];
    atomicAdd(&g_deg[d], wv);
    int p = atomicAdd(&g_cnt[d], 1);
    if (p < DSTR)
        g_edge[d * DSTR + p] = ((ull)__float_as_uint(wv) << 32) | (uint)s;
}

/* dinv + prescaled X transposed to [t][n][b] (b contiguous per node) */
__global__ void k_dinv(const float* __restrict__ X) {
    pdl_wait();
    int i = blockIdx.x * blockDim.x + threadIdx.x;
    if (i >= NN) return;
    float dv = rsqrtf(g_deg[i] + 1.0f);   /* self-loop weight 1 => deg>0 */
    g_dinv[i] = dv;
    const float2* xp = (const float2*)X;
#pragma unroll
    for (int t = 0; t < TS; t++)
#pragma unroll
        for (int b = 0; b < BB; b++) {
            float2 x = xp[(size_t)(b * TT + T0 + t) * NN + i];
            g_Xs[((size_t)t * NN + i) * BB + b] = make_float2(dv * x.x, dv * x.y);
        }
}

/* ------- fused stage A: agg of Xs (coalesced b-contiguous) + h1' -> fp16 -- */
__global__ __launch_bounds__(128) void k_aggAH1(const float* __restrict__ W1,
                                                const float* __restrict__ b1) {
    __shared__ __align__(16) uint4 sS[128][9];      /* staged rows, pad */
    __shared__ __align__(16) float sW1[128];
    __shared__ __align__(16) float sb1[64];
    int tid = threadIdx.x;
    if (tid < 128) sW1[tid] = W1[tid];      /* independent prologue */
    if (tid < 64)  sb1[tid] = b1[tid];
    __syncthreads();
    pdl_wait();                              /* before reading deg/dinv/Xs */

    int blk0 = blockIdx.x * 128;
    int idx = blk0 + tid;
    {
        int b = idx & 7;
        int nt = idx >> 3;
        int n = nt % NN;
        int t = nt / NN;
        /* [t][n][b]: 8 b-lanes of a node group read 64 contiguous bytes */
        const float2* base = g_Xs + (size_t)t * NN * BB + b;
        float dvd = g_dinv[n];
        float2 xn = base[n * BB];
        float ax = xn.x, ay = xn.y;          /* self term = Xs[n] */
        int cnt = g_cnt[n]; if (cnt > DSTR) cnt = DSTR;
        const ull* ep = g_edge + n * DSTR;
        int j = 0;
        for (; j + 4 <= cnt; j += 4) {
            ull e0 = ep[j], e1 = ep[j + 1], e2 = ep[j + 2], e3 = ep[j + 3];
            int s0 = (int)(e0 & 0xffffffffu);
            int s1 = (int)(e1 & 0xffffffffu);
            int s2 = (int)(e2 & 0xffffffffu);
            int s3 = (int)(e3 & 0xffffffffu);
            float2 x0 = base[s0 * BB], x1 = base[s1 * BB];
            float2 x2 = base[s2 * BB], x3 = base[s3 * BB];
            float w0 = __uint_as_float((uint)(e0 >> 32));
            float w1 = __uint_as_float((uint)(e1 >> 32));
            float w2 = __uint_as_float((uint)(e2 >> 32));
            float w3 = __uint_as_float((uint)(e3 >> 32));
            ax = fmaf(w0, x0.x, ax); ay = fmaf(w0, x0.y, ay);
            ax = fmaf(w1, x1.x, ax); ay = fmaf(w1, x1.y, ay);
            ax = fmaf(w2, x2.x, ax); ay = fmaf(w2, x2.y, ay);
            ax = fmaf(w3, x3.x, ax); ay = fmaf(w3, x3.y, ay);
        }
        for (; j < cnt; j++) {
            ull e = ep[j];
            int s = (int)(e & 0xffffffffu);
            float wv = __uint_as_float((uint)(e >> 32));
            float2 xs = base[s * BB];
            ax = fmaf(wv, xs.x, ax);
            ay = fmaf(wv, xs.y, ay);
        }
        ax *= dvd; ay *= dvd;                /* final dinv[d] scale */
        const float4* w0 = (const float4*)sW1;
        const float4* w1 = (const float4*)(sW1 + 64);
        const float4* bb = (const float4*)sb1;
#pragma unroll
        for (int q8 = 0; q8 < 8; q8++) {
            uint4 o;
            uint* op = (uint*)&o;
#pragma unroll
            for (int h = 0; h < 4; h++) {
                int q = q8 * 2 + (h >> 1);
                float4 W0 = w0[q], W1v = w1[q], Bv = bb[q];
                float v0, v1;
                if ((h & 1) == 0) {
                    v0 = fmaxf(fmaf(ax, W0.x, fmaf(ay, W1v.x, Bv.x)), 0.f);
                    v1 = fmaxf(fmaf(ax, W0.y, fmaf(ay, W1v.y, Bv.y)), 0.f);
                } else {
                    v0 = fmaxf(fmaf(ax, W0.z, fmaf(ay, W1v.z, Bv.z)), 0.f);
                    v1 = fmaxf(fmaf(ax, W0.w, fmaf(ay, W1v.w, Bv.w)), 0.f);
                }
                /* store h1' = dinv[n] * relu(h1): pre-scale for stage C */
                __half2 hh = __floats2half2_rn(dvd * v0, dvd * v1);
                op[h] = *(uint*)&hh;
            }
            sS[tid][q8] = o;
        }
    }
    __syncthreads();
    /* coalesced copy-out: block rows contiguous in g_h1h (8 uint4/row) */
    uint4* dst = g_h1h + (size_t)blk0 * 8;
    for (int i = tid; i < 128 * 8; i += 128) {
        int r = i >> 3, c = i & 7;
        dst[i] = sS[r][c];
    }
}

/* ------- fused: fp16 gather of h1' (no per-edge dinv) + W2 GEMM ----------- */
__device__ __forceinline__ void acc_row(const uint4* h1t, int s, int lane,
                                        float nr, float* aA, float* aB) {
    const uint4* rs = h1t + (size_t)s * 64 + lane;
    uint4 v0 = rs[0], v1 = rs[32];
    const __half2* p0 = (const __half2*)&v0;
    const __half2* p1 = (const __half2*)&v1;
#pragma unroll
    for (int k = 0; k < 4; k++) {
        float2 f0 = __half22float2(p0[k]);
        float2 f1 = __half22float2(p1[k]);
        aA[2 * k]     = fmaf(nr, f0.x, aA[2 * k]);
        aA[2 * k + 1] = fmaf(nr, f0.y, aA[2 * k + 1]);
        aB[2 * k]     = fmaf(nr, f1.x, aB[2 * k]);
        aB[2 * k + 1] = fmaf(nr, f1.y, aB[2 * k + 1]);
    }
}

__global__ __launch_bounds__(256) void k_aggCF1(const float* __restrict__ W2,
                                                const float* __restrict__ b2) {
    __shared__ float sC[64 * 65];          /* [r][ci] pad 65; reused for stores */
    __shared__ __align__(16) float sW2[4096];
    int tid = threadIdx.x;
    int t = blockIdx.y;
    for (int i = tid; i < 1024; i += 256)       /* independent prologue */
        ((float4*)sW2)[i] = ((const float4*)W2)[i];
    pdl_wait();                                  /* before reading h1/edges */

    int warp = tid >> 5, lane = tid & 31;
    int wi = blockIdx.x * 8 + warp;

    const uint4* h1t = g_h1h + (size_t)t * NN * 64;
    const uint4* rn = h1t + (size_t)wi * 64 + lane;
    float dvd = g_dinv[wi];
    float aA[8], aB[8];
    {
        /* self term = h1'[wi] (already dinv-scaled once) */
        uint4 v0 = rn[0], v1 = rn[32];
        const __half2* p0 = (const __half2*)&v0;
        const __half2* p1 = (const __half2*)&v1;
#pragma unroll
        for (int k = 0; k < 4; k++) {
            float2 f0 = __half22float2(p0[k]);
            float2 f1 = __half22float2(p1[k]);
            aA[2 * k]     = f0.x;
            aA[2 * k + 1] = f0.y;
            aB[2 * k]     = f1.x;
            aB[2 * k + 1] = f1.y;
        }
    }
    int cnt = g_cnt[wi]; if (cnt > DSTR) cnt = DSTR;
    const ull* ep = g_edge + wi * DSTR;
    int j = 0;
    for (; j + 2 <= cnt; j += 2) {
        ull e0 = ep[j], e1 = ep[j + 1];
        int s0 = (int)(e0 & 0xffffffffu);
        int s1 = (int)(e1 & 0xffffffffu);
        float w0v = __uint_as_float((uint)(e0 >> 32));
        float w1v = __uint_as_float((uint)(e1 >> 32));
        const uint4* rs0 = h1t + (size_t)s0 * 64 + lane;
        const uint4* rs1 = h1t + (size_t)s1 * 64 + lane;
        uint4 a0 = rs0[0], a1 = rs0[32];
        uint4 b0 = rs1[0], b1 = rs1[32];
        {
            const __half2* p0 = (const __half2*)&a0;
            const __half2* p1 = (const __half2*)&a1;
            const __half2* q0 = (const __half2*)&b0;
            const __half2* q1 = (const __half2*)&b1;
#pragma unroll
            for (int k = 0; k < 4; k++) {
                float2 f0 = __half22float2(p0[k]);
                float2 f1 = __half22float2(p1[k]);
                float2 g0 = __half22float2(q0[k]);
                float2 g1 = __half22float2(q1[k]);
                aA[2 * k]     = fmaf(w0v, f0.x, aA[2 * k]);
                aA[2 * k + 1] = fmaf(w0v, f0.y, aA[2 * k + 1]);
                aB[2 * k]     = fmaf(w0v, f1.x, aB[2 * k]);
                aB[2 * k + 1] = fmaf(w0v, f1.y, aB[2 * k + 1]);
                aA[2 * k]     = fmaf(w1v, g0.x, aA[2 * k]);
                aA[2 * k + 1] = fmaf(w1v, g0.y, aA[2 * k + 1]);
                aB[2 * k]     = fmaf(w1v, g1.x, aB[2 * k]);
                aB[2 * k + 1] = fmaf(w1v, g1.y, aB[2 * k + 1]);
            }
        }
    }
    if (j < cnt) {
        ull e = ep[j];
        int s = (int)(e & 0xffffffffu);
        float wv = __uint_as_float((uint)(e >> 32));
        acc_row(h1t, s, lane, wv, aA, aB);
    }
    /* final dinv[d] scale, then stage */
    {
        int bl = lane >> 3;
        int f0 = (lane & 7) * 8;
        float* pA = sC + (warp * 8 + bl) * 65 + f0;
        float* pB = sC + (warp * 8 + 4 + bl) * 65 + f0;
#pragma unroll
        for (int k = 0; k < 8; k++) { pA[k] = dvd * aA[k]; pB[k] = dvd * aB[k]; }
    }
    __syncthreads();

    int r2 = tid & 31, g = tid >> 5;
    ull accA[4], accB[4];
#pragma unroll
    for (int k = 0; k < 4; k++) {
        float2 bbv = __ldg((const float2*)b2 + g * 4 + k);
        accA[k] = pk2(bbv.x, bbv.y);
        accB[k] = accA[k];
    }
    const float* cA = sC + r2 * 65;
    const float* cB = sC + (r2 + 32) * 65;
#pragma unroll 4
    for (int ci = 0; ci < 64; ci++) {
        ull xA = bc2(cA[ci]);
        ull xB = bc2(cB[ci]);
        const ulonglong2* wp = (const ulonglong2*)(sW2 + ci * 64 + g * 8);
        ulonglong2 wa = wp[0], wb = wp[1];
        accA[0] = fma2(xA, wa.x, accA[0]);
        accA[1] = fma2(xA, wa.y, accA[1]);
        accA[2] = fma2(xA, wb.x, accA[2]);
        accA[3] = fma2(xA, wb.y, accA[3]);
        accB[0] = fma2(xB, wa.x, accB[0]);
        accB[1] = fma2(xB, wa.y, accB[1]);
        accB[2] = fma2(xB, wb.x, accB[2]);
        accB[3] = fma2(xB, wb.y, accB[3]);
    }
    __syncthreads();   /* all GEMM reads of sC done; reuse as half buffer */

    /* stage results as half into sC: [64 rows][pitch 66 halves] */
    __half* sH = (__half*)sC;
#pragma unroll
    for (int k = 0; k < 4; k++) {
        int col = g * 8 + 2 * k;
        float2 u = unp(accA[k]);
        float2 v = unp(accB[k]);
        *(__half2*)(sH + r2 * 66 + col) =
            __floats2half2_rn(fmaxf(u.x, 0.f), fmaxf(u.y, 0.f));
        *(__half2*)(sH + (r2 + 32) * 66 + col) =
            __floats2half2_rn(fmaxf(v.x, 0.f), fmaxf(v.y, 0.f));
    }
    __syncthreads();

    /* coalesced copy-out: 64 rows x 32 uints each */
    size_t nb0 = (size_t)blockIdx.x * 64;
    const uint* sU = (const uint*)sC;
    for (int i = tid; i < 2048; i += 256) {
        int r = i >> 5, cu = i & 31;
        uint v = sU[r * 33 + cu];
        ((uint*)g_h2h)[(nb0 + r) * (KD / 2) + t * 32 + cu] = v;
    }
}

/* ---------------- F2: tensor-core temporal convs + head ------------------- */
#define F2_SMEM (128*P1*2 + 128*P1*2 + 128*P2*2 + 64*P2*2 + (128+64+64)*4)
__global__ __launch_bounds__(256, 1) void k_f2(const float* __restrict__ tc1b,
                                               const float* __restrict__ tc2b,
                                               const float* __restrict__ ow,
                                               const float* __restrict__ ob,
                                               float* __restrict__ out) {
    extern __shared__ __align__(16) char smraw[];
    __half* A_s  = (__half*)smraw;                       /* [128][P1] */
    __half* B1t  = A_s + 128 * P1;                       /* [128][P1] */
    __half* A2   = B1t + 128 * P1;                       /* [128][P2] */
    __half* B2t  = A2 + 128 * P2;                        /* [64][P2]  */
    float*  sb1f = (float*)(B2t + 64 * P2);              /* [128] */
    float*  sb2f = sb1f + 128;                           /* [64] */
    float*  ows  = sb2f + 64;                            /* [64] */

    int tid = threadIdx.x;
    int blk = blockIdx.x;

    /* independent prologue: weights + biases (prepW transitively complete) */
    {
        const uint4* s1 = (const uint4*)g_B1h;
        uint4* d1 = (uint4*)B1t;
        for (int i = tid; i < 128 * P1 / 8; i += 256) d1[i] = s1[i];
        const uint4* s2 = (const uint4*)g_B2h;
        uint4* d2 = (uint4*)B2t;
        for (int i = tid; i < 64 * P2 / 8; i += 256) d2[i] = s2[i];
    }
    if (tid < 128) sb1f[tid] = tc1b[tid & 63];
    else if (tid < 192) sb2f[tid - 128] = tc2b[tid - 128];
    else if (tid < 256) ows[tid - 192] = ow[tid - 192];
    pdl_wait();                       /* before reading g_h2h */
    {
        const uint4* src = (const uint4*)(g_h2h + (size_t)blk * 128 * KD);
        for (int i = tid; i < 128 * 24; i += 256) {
            int r = i / 24, c = i % 24;
            ((uint4*)(A_s + r * P1))[c] = src[i];
        }
    }
    __syncthreads();

    int warp = tid >> 5, lane = tid & 31;
    int g = lane >> 2, tc = lane & 3;
    int m0 = warp * 16;
    int rA = (m0 + g) * P1, rA8 = (m0 + g + 8) * P1;

    float c1[16][4];
#pragma unroll
    for (int nt = 0; nt < 16; nt++) {
        float bb0 = sb1f[nt * 8 + 2 * tc];
        float bb1 = sb1f[nt * 8 + 2 * tc + 1];
        c1[nt][0] = bb0; c1[nt][1] = bb1; c1[nt][2] = bb0; c1[nt][3] = bb1;
    }
#pragma unroll
    for (int k0 = 0; k0 < 12; k0++) {
        int kc = k0 * 16 + 2 * tc;
        uint a0 = *(const uint*)(A_s + rA + kc);
        uint a1 = *(const uint*)(A_s + rA8 + kc);
        uint a2 = *(const uint*)(A_s + rA + kc + 8);
        uint a3 = *(const uint*)(A_s + rA8 + kc + 8);
#pragma unroll
        for (int nt = 0; nt < 16; nt++) {
            const __half* bp = B1t + (nt * 8 + g) * P1 + kc;
            uint b0 = *(const uint*)bp;
            uint b1 = *(const uint*)(bp + 8);
            mma16816(c1[nt][0], c1[nt][1], c1[nt][2], c1[nt][3],
                     a0, a1, a2, a3, b0, b1);
        }
    }
    {
        __half* w0 = A2 + (m0 + g) * P2;
        __half* w8 = A2 + (m0 + g + 8) * P2;
#pragma unroll
        for (int nt = 0; nt < 16; nt++) {
            int col = nt * 8 + 2 * tc;
            *(__half2*)(w0 + col) = __floats2half2_rn(fmaxf(c1[nt][0], 0.f),
                                                      fmaxf(c1[nt][1], 0.f));
            *(__half2*)(w8 + col) = __floats2half2_rn(fmaxf(c1[nt][2], 0.f),
                                                      fmaxf(c1[nt][3], 0.f));
        }
    }
    __syncwarp();

    float c2[8][4];
#pragma unroll
    for (int nt = 0; nt < 8; nt++) {
        float bb0 = sb2f[nt * 8 + 2 * tc];
        float bb1 = sb2f[nt * 8 + 2 * tc + 1];
        c2[nt][0] = bb0; c2[nt][1] = bb1; c2[nt][2] = bb0; c2[nt][3] = bb1;
    }
    int r2A = (m0 + g) * P2, r2A8 = (m0 + g + 8) * P2;
#pragma unroll
    for (int k0 = 0; k0 < 8; k0++) {
        int kc = k0 * 16 + 2 * tc;
        uint a0 = *(const uint*)(A2 + r2A + kc);
        uint a1 = *(const uint*)(A2 + r2A8 + kc);
        uint a2 = *(const uint*)(A2 + r2A + kc + 8);
        uint a3 = *(const uint*)(A2 + r2A8 + kc + 8);
#pragma unroll
        for (int nt = 0; nt < 8; nt++) {
            const __half* bp = B2t + (nt * 8 + g) * P2 + kc;
            uint b0 = *(const uint*)bp;
            uint b1 = *(const uint*)(bp + 8);
            mma16816(c2[nt][0], c2[nt][1], c2[nt][2], c2[nt][3],
                     a0, a1, a2, a3, b0, b1);
        }
    }
    float accR = 0.f, accR8 = 0.f;
#pragma unroll
    for (int nt = 0; nt < 8; nt++) {
        int col = nt * 8 + 2 * tc;
        float w0 = ows[col], w1 = ows[col + 1];
        accR  = fmaf(fmaxf(c2[nt][0], 0.f), w0, accR);
        accR  = fmaf(fmaxf(c2[nt][1], 0.f), w1, accR);
        accR8 = fmaf(fmaxf(c2[nt][2], 0.f), w0, accR8);
        accR8 = fmaf(fmaxf(c2[nt][3], 0.f), w1, accR8);
    }
    accR  += __shfl_xor_sync(0xffffffffu, accR, 1);
    accR  += __shfl_xor_sync(0xffffffffu, accR, 2);
    accR8 += __shfl_xor_sync(0xffffffffu, accR8, 1);
    accR8 += __shfl_xor_sync(0xffffffffu, accR8, 2);
    if (tc == 0) {
        float ob0 = __ldg(ob);
        int nb1 = blk * 128 + m0 + g;
        int nb2 = nb1 + 8;
        out[(nb1 & 7) * NN + (nb1 >> 3)] = accR + ob0;
        out[(nb2 & 7) * NN + (nb2 >> 3)] = accR8 + ob0;
    }
}

/* ---------------- launch helpers ---------------- */
template <typename F, typename... A>
static void lp(F f, dim3 g, dim3 b, size_t sm, bool pdl, A... args) {
    cudaLaunchConfig_t cfg = {};
    cfg.gridDim = g;
    cfg.blockDim = b;
    cfg.dynamicSmemBytes = sm;
    cfg.stream = 0;
    cudaLaunchAttribute attr[1];
    if (pdl) {
        attr[0].id = cudaLaunchAttributeProgrammaticStreamSerialization;
        attr[0].val.programmaticStreamSerializationAllowed = 1;
        cfg.attrs = attr;
        cfg.numAttrs = 1;
    }
    cudaError_t e = cudaLaunchKernelEx(&cfg, f, args...);
    if (e != cudaSuccess) {
        f<<<g, b, sm>>>(args...);   /* fallback: plain serialized launch */
    }
}

extern "C" void kernel_launch(void* const* d_in, const int* in_sizes, int n_in,
                              void* d_out, int out_size) {
    const float* X    = (const float*)d_in[0];
    const int*   ei   = (const int*)d_in[1];
    const float* ew   = (const float*)d_in[2];
    const float* W1   = (const float*)d_in[3];
    const float* b1   = (const float*)d_in[4];
    const float* W2   = (const float*)d_in[5];
    const float* b2   = (const float*)d_in[6];
    const float* tc1w = (const float*)d_in[7];
    const float* tc1b = (const float*)d_in[8];
    const float* tc2w = (const float*)d_in[9];
    const float* tc2b = (const float*)d_in[10];
    const float* ow   = (const float*)d_in[11];
    const float* ob   = (const float*)d_in[12];
    float* out = (float*)d_out;

    cudaFuncSetAttribute(k_f2, cudaFuncAttributeMaxDynamicSharedMemorySize, F2_SMEM);

    lp(k_prepW,  dim3(32), dim3(256), 0, false, tc1w, tc2w);
    lp(k_deg,    dim3((EE + 255) / 256), dim3(256), 0, true, ei, ew);
    lp(k_dinv,   dim3((NN + 255) / 256), dim3(256), 0, true, X);
    lp(k_aggAH1, dim3(ROWS / 128), dim3(128), 0, true, W1, b1);
    lp(k_aggCF1, dim3(NN / 8, TS), dim3(256), 0, true, W2, b2);
    lp(k_f2,     dim3(NB / 128), dim3(256), F2_SMEM, true, tc1b, tc2b, ow, ob, out);
}